// round 16
// baseline (speedup 1.0000x reference)
#include <cuda_runtime.h>
#include <cuda_fp16.h>
#include <cstdint>
#include <cstddef>

#define DH __host__ __device__

DH constexpr double tcos_core(double x) {
    double x2 = x * x, t = 1.0, s = 1.0;
    for (int i = 1; i <= 12; i++) { t *= -x2 / (double)((2 * i - 1) * (2 * i)); s += t; }
    return s;
}
// cos((2p+1) * f * pi / (2N)) with exact integer reduction.
DH constexpr double dcosg(int f, int p, int N) {
    int m = ((2 * p + 1) * f) % (4 * N);
    double sg = 1.0;
    if (m > 2 * N) m = 4 * N - m;
    if (m > N) { sg = -1.0; m = 2 * N - m; }
    const double PI = 3.14159265358979323846264338327950288;
    return sg * tcos_core((double)m * PI / (2.0 * N));
}
DH constexpr double rsqrt2c() {
    double g = 0.7;
    for (int i = 0; i < 50; i++) g = 0.5 * (g + 0.5 / g);
    return g;
}
// Stage factor: S=0 vertical (fold c_v), S=1 horizontal (fold c_u and 2/32).
DH constexpr double facs(int S, int v) {
    double f = (v == 0) ? rsqrt2c() : 1.0;
    return S ? f * (1.0 / 16.0) : f;
}
// Level-3 split of the 32-point DCT-II.
DH constexpr float codd(int S, int w, int p) { return (float)(dcosg(2 * w + 1, p, 32) * facs(S, 2 * w + 1)); }
DH constexpr float ceo8(int S, int t, int q) { return (float)(dcosg(2 * t + 1, q, 16) * facs(S, 4 * t + 2)); }
DH constexpr float ce4e(int S, int r, int q) { return (float)(dcosg(r,         q,  4) * facs(S, 8 * r)); }
DH constexpr float ce4o(int S, int r, int q) { return (float)(dcosg(2 * r + 1, q,  8) * facs(S, 8 * r + 4)); }

// ---- odd part: d[16] -> ao[16] ----
template <int S, int P, int W> struct OddW {
    static __device__ __forceinline__ void run(float dv, float (&a)[16]) {
        a[W] = fmaf(dv, codd(S, W, P), a[W]); OddW<S, P, W + 1>::run(dv, a);
    }
};
template <int S, int P> struct OddW<S, P, 16> { static __device__ __forceinline__ void run(float, float (&)[16]) {} };
template <int S, int P> struct OddIn {
    static __device__ __forceinline__ void run(const float (&d)[16], float (&a)[16]) {
        OddW<S, P, 0>::run(d[P], a); OddIn<S, P + 1>::run(d, a);
    }
};
template <int S> struct OddIn<S, 16> { static __device__ __forceinline__ void run(const float (&)[16], float (&)[16]) {} };

// ---- even-odd part: sd[8] -> ao2[8] ----
template <int S, int Q, int T> struct Eo8W {
    static __device__ __forceinline__ void run(float v, float (&a)[8]) {
        a[T] = fmaf(v, ceo8(S, T, Q), a[T]); Eo8W<S, Q, T + 1>::run(v, a);
    }
};
template <int S, int Q> struct Eo8W<S, Q, 8> { static __device__ __forceinline__ void run(float, float (&)[8]) {} };
template <int S, int Q> struct Eo8In {
    static __device__ __forceinline__ void run(const float (&sd)[8], float (&a)[8]) {
        Eo8W<S, Q, 0>::run(sd[Q], a); Eo8In<S, Q + 1>::run(sd, a);
    }
};
template <int S> struct Eo8In<S, 8> { static __device__ __forceinline__ void run(const float (&)[8], float (&)[8]) {} };

// ---- level-3: sss[4] -> aee[4] (v=8r), ssd[4] -> aoo[4] (v=8r+4) ----
template <int S, int Q, int R> struct E4W {
    static __device__ __forceinline__ void run(float se, float so, float (&aee)[4], float (&aoo)[4]) {
        aee[R] = fmaf(se, ce4e(S, R, Q), aee[R]);
        aoo[R] = fmaf(so, ce4o(S, R, Q), aoo[R]);
        E4W<S, Q, R + 1>::run(se, so, aee, aoo);
    }
};
template <int S, int Q> struct E4W<S, Q, 4> { static __device__ __forceinline__ void run(float, float, float (&)[4], float (&)[4]) {} };
template <int S, int Q> struct E4In {
    static __device__ __forceinline__ void run(const float (&sss)[4], const float (&ssd)[4],
                                               float (&aee)[4], float (&aoo)[4]) {
        E4W<S, Q, 0>::run(sss[Q], ssd[Q], aee, aoo); E4In<S, Q + 1>::run(sss, ssd, aee, aoo);
    }
};
template <int S> struct E4In<S, 4> { static __device__ __forceinline__ void run(const float (&)[4], const float (&)[4], float (&)[4], float (&)[4]) {} };

// Full 32-point DCT-II core from s/d arrays -> out[32] (v-indexed).
template <int S>
__device__ __forceinline__ void dct32_core(const float (&s)[16], const float (&d)[16], float (&out)[32]) {
    float ao[16];
    #pragma unroll
    for (int w = 0; w < 16; w++) ao[w] = 0.f;
    OddIn<S, 0>::run(d, ao);

    float ss[8], sd[8];
    #pragma unroll
    for (int q = 0; q < 8; q++) { ss[q] = s[q] + s[15 - q]; sd[q] = s[q] - s[15 - q]; }
    float ao2[8];
    #pragma unroll
    for (int t = 0; t < 8; t++) ao2[t] = 0.f;
    Eo8In<S, 0>::run(sd, ao2);

    float sss[4], ssd[4];
    #pragma unroll
    for (int q = 0; q < 4; q++) { sss[q] = ss[q] + ss[7 - q]; ssd[q] = ss[q] - ss[7 - q]; }
    float aee[4], aoo[4];
    #pragma unroll
    for (int r = 0; r < 4; r++) { aee[r] = 0.f; aoo[r] = 0.f; }
    E4In<S, 0>::run(sss, ssd, aee, aoo);

    #pragma unroll
    for (int w = 0; w < 16; w++) out[2 * w + 1] = ao[w];
    #pragma unroll
    for (int t = 0; t < 8; t++) out[4 * t + 2] = ao2[t];
    #pragma unroll
    for (int r = 0; r < 4; r++) { out[8 * r] = aee[r]; out[8 * r + 4] = aoo[r]; }
}

// ---- permutation derivation from the kernels input ----
__device__ int g_pos[1024];  // pos[v*32+u] = output channel index k

__device__ __forceinline__ unsigned long long lanemax_ull(unsigned long long k) {
    #pragma unroll
    for (int o = 16; o; o >>= 1) {
        unsigned long long v = __shfl_xor_sync(0xffffffffu, k, o);
        if (v > k) k = v;
    }
    return k;
}

__global__ void perm_kernel(const float* __restrict__ ker) {
    __shared__ float ctab[32][33];
    int tid = threadIdx.x;
    for (int i = tid; i < 1024; i += 256) {
        int f = i >> 5, x = i & 31;
        ctab[f][x] = cospif((float)((2 * x + 1) * f) * (1.0f / 64.0f));
    }
    __syncthreads();
    int k = blockIdx.x * 8 + (tid >> 5);
    int f = tid & 31;
    const float* K = ker + (size_t)k * 1024;
    float s = 0.f, t = 0.f;
    #pragma unroll
    for (int x = 0; x < 32; x++) { float c = ctab[f][x]; s = fmaf(K[x], c, s); t = fmaf(K[x * 32], c, t); }
    unsigned long long ks = (((unsigned long long)__float_as_uint(fabsf(s))) << 32) | (unsigned)f;
    unsigned long long kt = (((unsigned long long)__float_as_uint(fabsf(t))) << 32) | (unsigned)f;
    ks = lanemax_ull(ks); kt = lanemax_ull(kt);
    if (f == 0) g_pos[(int)(kt & 31u) * 32 + (int)(ks & 31u)] = k;
}

// ---- main fused kernel ----
// Grid: (ng=2, m=16, b=32). CTA = 256 threads, one 32-row x 256-col strip (8 blocks).
// tmp (fp16) planes: [c][v][x] at c*8704 + v*272 + (x/32)*34 + (x%31) halfs.
// pos_s: u16[32][36] padded rows (pair loads 4B-aligned, conflict-free).
// Mix is folded into stage 1 (each thread reads back only its own column —
// no barrier needed); PDL defers the g_pos dependency past stage 1.
static constexpr int ROW_HALFS = 272;
static constexpr int PLANE_HALFS = 32 * ROW_HALFS;    // 8704
static constexpr int TMP_HALFS = 3 * PLANE_HALFS;     // 26112 halfs = 52224 B
static constexpr int PLANE_H2 = PLANE_HALFS / 2;

__global__ void __launch_bounds__(256, 4)
dct_main(const float* __restrict__ rgb, float* __restrict__ out) {
    extern __shared__ __half tmp[];
    __shared__ unsigned short pos_s[32 * 36];

    const int tid = threadIdx.x;
    const int ng = blockIdx.x;
    const int m  = blockIdx.y;
    const int b  = blockIdx.z;

    // ---- stage 1: vertical level-3 DCT per RGB plane + in-column mix ----
    {
        const size_t plane = (size_t)512 * 512;
        const float* q0 = rgb + (size_t)b * 3 * plane + (size_t)(m * 32) * 512 + ng * 256 + tid;
        const int go = (tid >> 5) * 34 + (tid & 31);
        __half* tb0 = tmp + go;                       // R -> later 2Y
        __half* tb1 = tmp + PLANE_HALFS + go;         // G -> later Cb'
        __half* tb2 = tmp + 2 * PLANE_HALFS + go;     // (B) -> Cr'

        float o32[32];
        // R plane -> raw store
        {
            float s[16], d[16];
            #pragma unroll
            for (int P = 0; P < 16; P++) {
                float lo = __ldcs(q0 + P * 512), hi = __ldcs(q0 + (31 - P) * 512);
                s[P] = lo + hi; d[P] = lo - hi;
            }
            dct32_core<0>(s, d, o32);
            #pragma unroll
            for (int v = 0; v < 32; v++) tb0[v * ROW_HALFS] = __float2half_rn(o32[v]);
        }
        // G plane -> raw store
        {
            const float* q = q0 + plane;
            float s[16], d[16];
            #pragma unroll
            for (int P = 0; P < 16; P++) {
                float lo = __ldcs(q + P * 512), hi = __ldcs(q + (31 - P) * 512);
                s[P] = lo + hi; d[P] = lo - hi;
            }
            dct32_core<0>(s, d, o32);
            #pragma unroll
            for (int v = 0; v < 32; v++) tb1[v * ROW_HALFS] = __float2half_rn(o32[v]);
        }
        // B plane -> regs, then mix (reads back ONLY this thread's own column)
        {
            const float* q = q0 + 2 * plane;
            float s[16], d[16];
            #pragma unroll
            for (int P = 0; P < 16; P++) {
                float lo = __ldcs(q + P * 512), hi = __ldcs(q + (31 - P) * 512);
                s[P] = lo + hi; d[P] = lo - hi;
            }
            dct32_core<0>(s, d, o32);
            #pragma unroll
            for (int v = 0; v < 32; v++) {
                float r = __half2float(tb0[v * ROW_HALFS]);
                float g = __half2float(tb1[v * ROW_HALFS]);
                float bb = o32[v];
                float y0 = fmaf(0.299f, r, fmaf(0.587f, g, 0.114f * bb));
                tb0[v * ROW_HALFS] = __float2half_rn(2.0f * y0);
                tb1[v * ROW_HALFS] = __float2half_rn((bb - y0) * 1.128f);
                tb2[v * ROW_HALFS] = __float2half_rn((r - y0) * 1.426f);
            }
        }
    }

    // perm result only needed from here on; its kernel ran in our shadow.
    cudaGridDependencySynchronize();
    #pragma unroll
    for (int i = 0; i < 4; i++) {
        int idx = i * 256 + tid;
        pos_s[(idx >> 5) * 36 + (idx & 31)] = (unsigned short)g_pos[idx];
    }
    __syncthreads();

    // ---- stage 2: horizontal level-3 butterfly DCT. thread = (v, nblk), loop c. ----
    {
        const int v = tid >> 3, nblk = tid & 7;
        const int n = ng * 8 + nblk;
        float* ob = out + (((size_t)b * 3072) * 16 + m) * 16 + n;
        const uint32_t* pprow = reinterpret_cast<const uint32_t*>(pos_s + v * 36);

        #pragma unroll 1
        for (int c = 0; c < 3; c++) {
            const __half2* t2 = reinterpret_cast<const __half2*>(
                tmp + c * PLANE_HALFS + v * ROW_HALFS + nblk * 34);

            float vals[32];
            #pragma unroll
            for (int j = 0; j < 16; j++) {
                float2 f2 = __half22float2(t2[j]);
                vals[2 * j] = f2.x; vals[2 * j + 1] = f2.y;
            }
            float s[16], d[16];
            #pragma unroll
            for (int P = 0; P < 16; P++) {
                s[P] = vals[P] + vals[31 - P];
                d[P] = vals[P] - vals[31 - P];
            }

            float a2[32];
            dct32_core<1>(s, d, a2);

            if (c == 0 && v == 0) a2[0] -= 32.0f;   // DC term of the "-1" offset

            float* obc = ob + (size_t)c * 1024 * 256;
            #pragma unroll
            for (int j = 0; j < 16; j++) {
                uint32_t pk = pprow[j];
                __stcs(obc + (size_t)(pk & 0xFFFFu) * 256, a2[2 * j]);
                __stcs(obc + (size_t)(pk >> 16) * 256,     a2[2 * j + 1]);
            }
        }
    }
}

// ---------------- launch ----------------
extern "C" void kernel_launch(void* const* d_in, const int* in_sizes, int n_in,
                              void* d_out, int out_size) {
    const float* rgb = (const float*)d_in[0];
    const float* ker = (const float*)d_in[1];
    float* out = (float*)d_out;

    perm_kernel<<<128, 256>>>(ker);

    cudaFuncSetAttribute(dct_main, cudaFuncAttributeMaxDynamicSharedMemorySize,
                         TMP_HALFS * (int)sizeof(__half));

    cudaLaunchConfig_t cfg = {};
    cfg.gridDim = dim3(2, 16, 32);
    cfg.blockDim = dim3(256, 1, 1);
    cfg.dynamicSmemBytes = TMP_HALFS * (int)sizeof(__half);
    cfg.stream = 0;
    cudaLaunchAttribute attrs[1];
    attrs[0].id = cudaLaunchAttributeProgrammaticStreamSerialization;
    attrs[0].val.programmaticStreamSerializationAllowed = 1;
    cfg.attrs = attrs;
    cfg.numAttrs = 1;
    cudaLaunchKernelEx(&cfg, dct_main, rgb, out);
}

// round 17
// speedup vs baseline: 1.1147x; 1.1147x over previous
#include <cuda_runtime.h>
#include <cuda_fp16.h>
#include <cstdint>
#include <cstddef>

#define DH __host__ __device__

DH constexpr double tcos_core(double x) {
    double x2 = x * x, t = 1.0, s = 1.0;
    for (int i = 1; i <= 12; i++) { t *= -x2 / (double)((2 * i - 1) * (2 * i)); s += t; }
    return s;
}
// cos((2p+1) * f * pi / (2N)) with exact integer reduction.
DH constexpr double dcosg(int f, int p, int N) {
    int m = ((2 * p + 1) * f) % (4 * N);
    double sg = 1.0;
    if (m > 2 * N) m = 4 * N - m;
    if (m > N) { sg = -1.0; m = 2 * N - m; }
    const double PI = 3.14159265358979323846264338327950288;
    return sg * tcos_core((double)m * PI / (2.0 * N));
}
DH constexpr double rsqrt2c() {
    double g = 0.7;
    for (int i = 0; i < 50; i++) g = 0.5 * (g + 0.5 / g);
    return g;
}
// Stage factor: S=0 vertical (fold c_v), S=1 horizontal (fold c_u and 2/32).
DH constexpr double facs(int S, int v) {
    double f = (v == 0) ? rsqrt2c() : 1.0;
    return S ? f * (1.0 / 16.0) : f;
}
// Level-3 split of the 32-point DCT-II.
DH constexpr float codd(int S, int w, int p) { return (float)(dcosg(2 * w + 1, p, 32) * facs(S, 2 * w + 1)); }
DH constexpr float ceo8(int S, int t, int q) { return (float)(dcosg(2 * t + 1, q, 16) * facs(S, 4 * t + 2)); }
DH constexpr float ce4e(int S, int r, int q) { return (float)(dcosg(r,         q,  4) * facs(S, 8 * r)); }
DH constexpr float ce4o(int S, int r, int q) { return (float)(dcosg(2 * r + 1, q,  8) * facs(S, 8 * r + 4)); }

// ---- odd part: d[16] -> ao[16] ----
template <int S, int P, int W> struct OddW {
    static __device__ __forceinline__ void run(float dv, float (&a)[16]) {
        a[W] = fmaf(dv, codd(S, W, P), a[W]); OddW<S, P, W + 1>::run(dv, a);
    }
};
template <int S, int P> struct OddW<S, P, 16> { static __device__ __forceinline__ void run(float, float (&)[16]) {} };
template <int S, int P> struct OddIn {
    static __device__ __forceinline__ void run(const float (&d)[16], float (&a)[16]) {
        OddW<S, P, 0>::run(d[P], a); OddIn<S, P + 1>::run(d, a);
    }
};
template <int S> struct OddIn<S, 16> { static __device__ __forceinline__ void run(const float (&)[16], float (&)[16]) {} };

// ---- even-odd part: sd[8] -> ao2[8] ----
template <int S, int Q, int T> struct Eo8W {
    static __device__ __forceinline__ void run(float v, float (&a)[8]) {
        a[T] = fmaf(v, ceo8(S, T, Q), a[T]); Eo8W<S, Q, T + 1>::run(v, a);
    }
};
template <int S, int Q> struct Eo8W<S, Q, 8> { static __device__ __forceinline__ void run(float, float (&)[8]) {} };
template <int S, int Q> struct Eo8In {
    static __device__ __forceinline__ void run(const float (&sd)[8], float (&a)[8]) {
        Eo8W<S, Q, 0>::run(sd[Q], a); Eo8In<S, Q + 1>::run(sd, a);
    }
};
template <int S> struct Eo8In<S, 8> { static __device__ __forceinline__ void run(const float (&)[8], float (&)[8]) {} };

// ---- level-3: sss[4] -> aee[4] (v=8r), ssd[4] -> aoo[4] (v=8r+4) ----
template <int S, int Q, int R> struct E4W {
    static __device__ __forceinline__ void run(float se, float so, float (&aee)[4], float (&aoo)[4]) {
        aee[R] = fmaf(se, ce4e(S, R, Q), aee[R]);
        aoo[R] = fmaf(so, ce4o(S, R, Q), aoo[R]);
        E4W<S, Q, R + 1>::run(se, so, aee, aoo);
    }
};
template <int S, int Q> struct E4W<S, Q, 4> { static __device__ __forceinline__ void run(float, float, float (&)[4], float (&)[4]) {} };
template <int S, int Q> struct E4In {
    static __device__ __forceinline__ void run(const float (&sss)[4], const float (&ssd)[4],
                                               float (&aee)[4], float (&aoo)[4]) {
        E4W<S, Q, 0>::run(sss[Q], ssd[Q], aee, aoo); E4In<S, Q + 1>::run(sss, ssd, aee, aoo);
    }
};
template <int S> struct E4In<S, 4> { static __device__ __forceinline__ void run(const float (&)[4], const float (&)[4], float (&)[4], float (&)[4]) {} };

// Full 32-point DCT-II core from s/d arrays -> out[32] (v-indexed).
template <int S>
__device__ __forceinline__ void dct32_core(const float (&s)[16], const float (&d)[16], float (&out)[32]) {
    float ao[16];
    #pragma unroll
    for (int w = 0; w < 16; w++) ao[w] = 0.f;
    OddIn<S, 0>::run(d, ao);

    float ss[8], sd[8];
    #pragma unroll
    for (int q = 0; q < 8; q++) { ss[q] = s[q] + s[15 - q]; sd[q] = s[q] - s[15 - q]; }
    float ao2[8];
    #pragma unroll
    for (int t = 0; t < 8; t++) ao2[t] = 0.f;
    Eo8In<S, 0>::run(sd, ao2);

    float sss[4], ssd[4];
    #pragma unroll
    for (int q = 0; q < 4; q++) { sss[q] = ss[q] + ss[7 - q]; ssd[q] = ss[q] - ss[7 - q]; }
    float aee[4], aoo[4];
    #pragma unroll
    for (int r = 0; r < 4; r++) { aee[r] = 0.f; aoo[r] = 0.f; }
    E4In<S, 0>::run(sss, ssd, aee, aoo);

    #pragma unroll
    for (int w = 0; w < 16; w++) out[2 * w + 1] = ao[w];
    #pragma unroll
    for (int t = 0; t < 8; t++) out[4 * t + 2] = ao2[t];
    #pragma unroll
    for (int r = 0; r < 4; r++) { out[8 * r] = aee[r]; out[8 * r + 4] = aoo[r]; }
}

// ---- permutation derivation from the kernels input ----
__device__ int g_pos[1024];  // pos[v*32+u] = output channel index k

__device__ __forceinline__ unsigned long long lanemax_ull(unsigned long long k) {
    #pragma unroll
    for (int o = 16; o; o >>= 1) {
        unsigned long long v = __shfl_xor_sync(0xffffffffu, k, o);
        if (v > k) k = v;
    }
    return k;
}

__global__ void perm_kernel(const float* __restrict__ ker) {
    // Signal PDL consumers immediately: dct_main's stage 1 has no dependency
    // on g_pos and can co-run; its cudaGridDependencySynchronize() still waits
    // for this grid's completion before reading g_pos.
    cudaTriggerProgrammaticLaunchCompletion();

    __shared__ float ctab[32][33];
    int tid = threadIdx.x;
    for (int i = tid; i < 1024; i += 256) {
        int f = i >> 5, x = i & 31;
        ctab[f][x] = cospif((float)((2 * x + 1) * f) * (1.0f / 64.0f));
    }
    __syncthreads();
    int k = blockIdx.x * 8 + (tid >> 5);
    int f = tid & 31;
    const float* K = ker + (size_t)k * 1024;
    float s = 0.f, t = 0.f;
    #pragma unroll
    for (int x = 0; x < 32; x++) { float c = ctab[f][x]; s = fmaf(K[x], c, s); t = fmaf(K[x * 32], c, t); }
    unsigned long long ks = (((unsigned long long)__float_as_uint(fabsf(s))) << 32) | (unsigned)f;
    unsigned long long kt = (((unsigned long long)__float_as_uint(fabsf(t))) << 32) | (unsigned)f;
    ks = lanemax_ull(ks); kt = lanemax_ull(kt);
    if (f == 0) g_pos[(int)(kt & 31u) * 32 + (int)(ks & 31u)] = k;
}

// ---- main fused kernel ----
// Grid: (ng=2, m=16, b=32). CTA = 256 threads, one 32-row x 256-col strip (8 blocks).
// tmp (fp16) planes: [c][v][x] at c*9216 + v*288 + (x/32)*36 + (x%32) halfs
// (36-half groups = 72B: 8B-aligned for LDS.64 at every nblk, conflict-free).
// pos_s: u16[32][36] padded rows (pair loads 4B-aligned, conflict-free).
// Mix folded into stage 1 (thread reads back only its own column, no barrier).
static constexpr int ROW_HALFS = 288;
static constexpr int PLANE_HALFS = 32 * ROW_HALFS;    // 9216
static constexpr int TMP_HALFS = 3 * PLANE_HALFS;     // 27648 halfs = 55296 B

__global__ void __launch_bounds__(256, 4)
dct_main(const float* __restrict__ rgb, float* __restrict__ out) {
    extern __shared__ __half tmp[];
    __shared__ unsigned short pos_s[32 * 36];

    const int tid = threadIdx.x;
    const int ng = blockIdx.x;
    const int m  = blockIdx.y;
    const int b  = blockIdx.z;

    // ---- stage 1: vertical level-3 DCT per RGB plane + in-column mix ----
    {
        const size_t plane = (size_t)512 * 512;
        const float* q0 = rgb + (size_t)b * 3 * plane + (size_t)(m * 32) * 512 + ng * 256 + tid;
        const int go = (tid >> 5) * 36 + (tid & 31);
        __half* tb0 = tmp + go;                       // R -> later 2Y
        __half* tb1 = tmp + PLANE_HALFS + go;         // G -> later Cb'
        __half* tb2 = tmp + 2 * PLANE_HALFS + go;     // Cr'

        float o32[32];
        // R plane -> raw store
        {
            float s[16], d[16];
            #pragma unroll
            for (int P = 0; P < 16; P++) {
                float lo = __ldcs(q0 + P * 512), hi = __ldcs(q0 + (31 - P) * 512);
                s[P] = lo + hi; d[P] = lo - hi;
            }
            dct32_core<0>(s, d, o32);
            #pragma unroll
            for (int v = 0; v < 32; v++) tb0[v * ROW_HALFS] = __float2half_rn(o32[v]);
        }
        // G plane -> raw store
        {
            const float* q = q0 + plane;
            float s[16], d[16];
            #pragma unroll
            for (int P = 0; P < 16; P++) {
                float lo = __ldcs(q + P * 512), hi = __ldcs(q + (31 - P) * 512);
                s[P] = lo + hi; d[P] = lo - hi;
            }
            dct32_core<0>(s, d, o32);
            #pragma unroll
            for (int v = 0; v < 32; v++) tb1[v * ROW_HALFS] = __float2half_rn(o32[v]);
        }
        // B plane -> regs, then mix (reads back ONLY this thread's own column)
        {
            const float* q = q0 + 2 * plane;
            float s[16], d[16];
            #pragma unroll
            for (int P = 0; P < 16; P++) {
                float lo = __ldcs(q + P * 512), hi = __ldcs(q + (31 - P) * 512);
                s[P] = lo + hi; d[P] = lo - hi;
            }
            dct32_core<0>(s, d, o32);
            #pragma unroll
            for (int v = 0; v < 32; v++) {
                float r = __half2float(tb0[v * ROW_HALFS]);
                float g = __half2float(tb1[v * ROW_HALFS]);
                float bb = o32[v];
                float y0 = fmaf(0.299f, r, fmaf(0.587f, g, 0.114f * bb));
                tb0[v * ROW_HALFS] = __float2half_rn(2.0f * y0);
                tb1[v * ROW_HALFS] = __float2half_rn((bb - y0) * 1.128f);
                tb2[v * ROW_HALFS] = __float2half_rn((r - y0) * 1.426f);
            }
        }
    }

    // perm result only needed from here on; perm ran in our shadow (PDL).
    cudaGridDependencySynchronize();
    #pragma unroll
    for (int i = 0; i < 4; i++) {
        int idx = i * 256 + tid;
        pos_s[(idx >> 5) * 36 + (idx & 31)] = (unsigned short)g_pos[idx];
    }
    __syncthreads();

    // ---- stage 2: horizontal level-3 butterfly DCT. thread = (v, nblk), loop c. ----
    {
        const int v = tid >> 3, nblk = tid & 7;
        const int n = ng * 8 + nblk;
        float* ob = out + (((size_t)b * 3072) * 16 + m) * 16 + n;
        const uint32_t* pprow = reinterpret_cast<const uint32_t*>(pos_s + v * 36);

        #pragma unroll 1
        for (int c = 0; c < 3; c++) {
            const uint2* t64 = reinterpret_cast<const uint2*>(
                tmp + c * PLANE_HALFS + v * ROW_HALFS + nblk * 36);

            float vals[32];
            #pragma unroll
            for (int j = 0; j < 8; j++) {
                uint2 w = t64[j];
                __half2 h0 = *reinterpret_cast<__half2*>(&w.x);
                __half2 h1 = *reinterpret_cast<__half2*>(&w.y);
                float2 f0 = __half22float2(h0), f1 = __half22float2(h1);
                vals[4 * j] = f0.x; vals[4 * j + 1] = f0.y;
                vals[4 * j + 2] = f1.x; vals[4 * j + 3] = f1.y;
            }
            float s[16], d[16];
            #pragma unroll
            for (int P = 0; P < 16; P++) {
                s[P] = vals[P] + vals[31 - P];
                d[P] = vals[P] - vals[31 - P];
            }

            float a2[32];
            dct32_core<1>(s, d, a2);

            if (c == 0 && v == 0) a2[0] -= 32.0f;   // DC term of the "-1" offset

            float* obc = ob + (size_t)c * 1024 * 256;
            #pragma unroll
            for (int j = 0; j < 16; j++) {
                uint32_t pk = pprow[j];
                __stcs(obc + (size_t)(pk & 0xFFFFu) * 256, a2[2 * j]);
                __stcs(obc + (size_t)(pk >> 16) * 256,     a2[2 * j + 1]);
            }
        }
    }
}

// ---------------- launch ----------------
extern "C" void kernel_launch(void* const* d_in, const int* in_sizes, int n_in,
                              void* d_out, int out_size) {
    const float* rgb = (const float*)d_in[0];
    const float* ker = (const float*)d_in[1];
    float* out = (float*)d_out;

    perm_kernel<<<128, 256>>>(ker);

    cudaFuncSetAttribute(dct_main, cudaFuncAttributeMaxDynamicSharedMemorySize,
                         TMP_HALFS * (int)sizeof(__half));

    cudaLaunchConfig_t cfg = {};
    cfg.gridDim = dim3(2, 16, 32);
    cfg.blockDim = dim3(256, 1, 1);
    cfg.dynamicSmemBytes = TMP_HALFS * (int)sizeof(__half);
    cfg.stream = 0;
    cudaLaunchAttribute attrs[1];
    attrs[0].id = cudaLaunchAttributeProgrammaticStreamSerialization;
    attrs[0].val.programmaticStreamSerializationAllowed = 1;
    cfg.attrs = attrs;
    cfg.numAttrs = 1;
    cudaLaunchKernelEx(&cfg, dct_main, rgb, out);
}